// round 5
// baseline (speedup 1.0000x reference)
#include <cuda_runtime.h>
#include <cuda_bf16.h>
#include <cstdint>
#include <math.h>

// ---------------- scratch -------------------------------------------------
__device__ float g_q [2048 * 1024];      // box_feats @ Wq^T
__device__ float g_k [2048 * 1024];      // part_feats @ Wk^T
__device__ float g_pw[1024 * 2048];      // pwT = conv_w @ part_feats^T  [GE, P]
__device__ float g_L [2048 * 16 * 1024]; // logits / softmax

// ---------------- helpers -------------------------------------------------
__device__ __forceinline__ uint32_t smem_u32(const void* p) {
    uint32_t a;
    asm("{ .reg .u64 t; cvta.to.shared.u64 t, %1; cvt.u32.u64 %0, t; }"
        : "=r"(a) : "l"(p));
    return a;
}
__device__ __forceinline__ uint32_t pack_bf(float lo, float hi) {
    uint32_t r;
    asm("cvt.rn.bf16x2.f32 %0, %1, %2;" : "=r"(r) : "f"(hi), "f"(lo));
    return r;
}
#define STS64(a, x, y) \
    asm volatile("st.shared.v2.b32 [%0], {%1, %2};" :: "r"(a), "r"(x), "r"(y) : "memory")

__device__ __forceinline__ void ldsm4(uint32_t* r, uint32_t addr) {
    asm volatile("ldmatrix.sync.aligned.m8n8.x4.shared.b16 {%0,%1,%2,%3}, [%4];"
        : "=r"(r[0]), "=r"(r[1]), "=r"(r[2]), "=r"(r[3]) : "r"(addr));
}
__device__ __forceinline__ void mma16816(float* d, const uint32_t* a, const uint32_t* b) {
    asm volatile(
        "mma.sync.aligned.m16n8k16.row.col.f32.bf16.bf16.f32 "
        "{%0,%1,%2,%3}, {%4,%5,%6,%7}, {%8,%9}, {%0,%1,%2,%3};"
        : "+f"(d[0]), "+f"(d[1]), "+f"(d[2]), "+f"(d[3])
        : "r"(a[0]), "r"(a[1]), "r"(a[2]), "r"(a[3]), "r"(b[0]), "r"(b[1]));
}

// ---------------- bf16-split tensor-core GEMM -----------------------------
// C[m,n] = alpha * sum_k A[m,k]*B[n,k] + bias[n]  (fp32 in/out, ~fp32 precision)
// 512 threads, WGM x WGN warp grid (16 warps), warp tile 32x32.
// SMEM rows 80B (32 bf16 + 16B pad) -> ldmatrix conflict-free.
template <int BM, int BN, int WGM, int WGN>
__global__ __launch_bounds__(512) void tgemm(
    const float* __restrict__ A, const float* __restrict__ B,
    const float* __restrict__ bias, float* __restrict__ C,
    int K, int lda, int ldb, int ldc,
    long long sA1, long long sA2, long long sB1, long long sB2,
    long long sC1, long long sC2, long long sBias2,
    int ngroup, float alpha)
{
    static_assert(WGM * WGN == 16, "");
    constexpr int A_MAT = BM * 80;
    constexpr int B_MAT = BN * 80;
    constexpr int BUFSZ = 2 * A_MAT + 2 * B_MAT;
    constexpr int NA4 = BM / 64;   // A float4 LDGs per thread
    constexpr int NB4 = BN / 64;   // B float4 LDGs per thread

    extern __shared__ char smem[];
    const uint32_t sb = smem_u32(smem);

    const int t = threadIdx.x;
    const int wid = t >> 5, lane = t & 31;
    const int wm = wid % WGM, wn = wid / WGM;

    const int z = blockIdx.z;
    const int bb = z / ngroup;
    const int gg = z - bb * ngroup;
    A += bb * sA1 + gg * sA2;
    B += bb * sB1 + gg * sB2;
    C += bb * sC1 + gg * sC2;
    if (bias) bias += gg * sBias2;

    const int m0 = blockIdx.y * BM;
    const int n0 = blockIdx.x * BN;

    float4 pa[NA4];
    float4 pb[NB4];

    auto ldgA = [&](int c) {
        const int k0 = c * 32;
#pragma unroll
        for (int r = 0; r < NA4; r++) {
            int f = r * 512 + t, row = f >> 3, seg = f & 7;
            pa[r] = *(const float4*)(A + (size_t)(m0 + row) * lda + k0 + seg * 4);
        }
    };
    auto ldgB = [&](int c) {
        const int k0 = c * 32;
#pragma unroll
        for (int r = 0; r < NB4; r++) {
            int f = r * 512 + t, row = f >> 3, seg = f & 7;
            pb[r] = *(const float4*)(B + (size_t)(n0 + row) * ldb + k0 + seg * 4);
        }
    };
    auto sts = [&](int buf) {
        const uint32_t base = sb + buf * BUFSZ;
#pragma unroll
        for (int r = 0; r < NA4; r++) {
            int f = r * 512 + t, row = f >> 3, seg = f & 7;
            float4 v = pa[r];
            uint32_t h01 = pack_bf(v.x, v.y);
            uint32_t h23 = pack_bf(v.z, v.w);
            float hx = __uint_as_float(h01 << 16);
            float hy = __uint_as_float(h01 & 0xFFFF0000u);
            float hz = __uint_as_float(h23 << 16);
            float hw = __uint_as_float(h23 & 0xFFFF0000u);
            uint32_t l01 = pack_bf(v.x - hx, v.y - hy);
            uint32_t l23 = pack_bf(v.z - hz, v.w - hw);
            uint32_t off = base + row * 80 + seg * 8;
            STS64(off, h01, h23);
            STS64(off + A_MAT, l01, l23);
        }
#pragma unroll
        for (int r = 0; r < NB4; r++) {
            int f = r * 512 + t, row = f >> 3, seg = f & 7;
            float4 v = pb[r];
            uint32_t h01 = pack_bf(v.x, v.y);
            uint32_t h23 = pack_bf(v.z, v.w);
            float hx = __uint_as_float(h01 << 16);
            float hy = __uint_as_float(h01 & 0xFFFF0000u);
            float hz = __uint_as_float(h23 << 16);
            float hw = __uint_as_float(h23 & 0xFFFF0000u);
            uint32_t l01 = pack_bf(v.x - hx, v.y - hy);
            uint32_t l23 = pack_bf(v.z - hz, v.w - hw);
            uint32_t off = base + 2 * A_MAT + row * 80 + seg * 8;
            STS64(off, h01, h23);
            STS64(off + B_MAT, l01, l23);
        }
    };

    float acc[2][4][4];
#pragma unroll
    for (int i = 0; i < 2; i++)
#pragma unroll
        for (int j = 0; j < 4; j++)
#pragma unroll
            for (int q = 0; q < 4; q++) acc[i][j][q] = 0.f;

    const uint32_t a_lane = (uint32_t)((lane & 15) * 80 + (lane >> 4) * 16);
    const uint32_t b_lane = (uint32_t)(((lane & 7) + ((lane >> 4) << 3)) * 80
                                       + ((lane >> 3) & 1) * 16);

    auto compute = [&](int buf) {
        const uint32_t base = sb + buf * BUFSZ;
#pragma unroll
        for (int ks = 0; ks < 2; ks++) {
            const uint32_t ko = ks * 32;
            uint32_t Ah[2][4], Al[2][4], Bh[4][2], Bl[4][2];
#pragma unroll
            for (int mb = 0; mb < 2; mb++) {
                uint32_t ad = base + (wm * 32 + mb * 16) * 80 + a_lane + ko;
                ldsm4(Ah[mb], ad);
                ldsm4(Al[mb], ad + A_MAT);
            }
#pragma unroll
            for (int n2 = 0; n2 < 2; n2++) {
                uint32_t bd = base + 2 * A_MAT + (wn * 32 + n2 * 16) * 80 + b_lane + ko;
                ldsm4(&Bh[2 * n2][0], bd);
                ldsm4(&Bl[2 * n2][0], bd + B_MAT);
            }
#pragma unroll
            for (int mb = 0; mb < 2; mb++)
#pragma unroll
                for (int nb = 0; nb < 4; nb++) {
                    mma16816(acc[mb][nb], Ah[mb], Bh[nb]);
                    mma16816(acc[mb][nb], Ah[mb], Bl[nb]);
                    mma16816(acc[mb][nb], Al[mb], Bh[nb]);
                }
        }
    };

    const int NC = K >> 5;
    ldgA(0); ldgB(0);
    sts(0);
    if (NC > 1) { ldgA(1); ldgB(1); }
    __syncthreads();

    // one barrier per iteration: sts writes buffer (c+1)&1 (last read at
    // iter c-1, protected by that iter's barrier), compute reads c&1.
    for (int c = 0; c < NC; c++) {
        if (c + 1 < NC) sts((c + 1) & 1);
        if (c + 2 < NC) { ldgA(c + 2); ldgB(c + 2); }
        compute(c & 1);
        __syncthreads();
    }

    // epilogue
    const int er = lane >> 2, ec = (lane & 3) * 2;
#pragma unroll
    for (int mb = 0; mb < 2; mb++) {
#pragma unroll
        for (int nb = 0; nb < 4; nb++) {
            const int m = m0 + wm * 32 + mb * 16 + er;
            const int n = n0 + wn * 32 + nb * 8 + ec;
            float b0 = 0.f, b1 = 0.f;
            if (bias) { b0 = bias[n]; b1 = bias[n + 1]; }
            float2 v0, v1;
            v0.x = alpha * acc[mb][nb][0] + b0;
            v0.y = alpha * acc[mb][nb][1] + b1;
            v1.x = alpha * acc[mb][nb][2] + b0;
            v1.y = alpha * acc[mb][nb][3] + b1;
            *(float2*)(C + (size_t)m * ldc + n) = v0;
            *(float2*)(C + (size_t)(m + 8) * ldc + n) = v1;
        }
    }
}

// ---------------- fused poslogit + softmax --------------------------------
__global__ __launch_bounds__(256) void fused_ps(
    const float* __restrict__ rois, const float* __restrict__ part_rois,
    const float* __restrict__ Wg_w, const float* __restrict__ Wg_b,
    float* __restrict__ L)
{
    extern __shared__ float fsm[];
    float* sm = fsm;                 // [16][1024]
    float* wg = fsm + 16 * 1024;     // [16][64]
    float* wb = wg + 1024;           // [16]

    const int t = threadIdx.x;
    for (int i = t; i < 1024; i += 256) wg[i] = Wg_w[i];
    if (t < 16) wb[t] = Wg_b[t];

    const int n = blockIdx.x;
    const int b = blockIdx.y;
    const int ng = b * 1024 + n;
    const size_t base = (size_t)ng * 16 * 1024;

    const float xmin = rois[ng * 5 + 1];
    const float ymin = rois[ng * 5 + 2];
    const float xmax = rois[ng * 5 + 3];
    const float ymax = rois[ng * 5 + 4];
    const float bw = xmax - xmin + 1.f;
    const float bh = ymax - ymin + 1.f;
    const float cx = 0.5f * (xmin + xmax);
    const float cy = 0.5f * (ymin + ymax);
    __syncthreads();

    const float inv_em[8] = {
        1.0f, 0.42169651f, 0.17782794f, 0.074989424f,
        0.031622777f, 0.013335215f, 0.0056234133f, 0.0023713737f};

#pragma unroll
    for (int cc = 0; cc < 4; cc++) {
        const int p = cc * 256 + t;
        const int pg = b * 1024 + p;
        const float pxmin = part_rois[pg * 5 + 1];
        const float pymin = part_rois[pg * 5 + 2];
        const float pxmax = part_rois[pg * 5 + 3];
        const float pymax = part_rois[pg * 5 + 4];
        const float pw = pxmax - pxmin + 1.f;
        const float ph = pymax - pymin + 1.f;
        const float pcx = 0.5f * (pxmin + pxmax);
        const float pcy = 0.5f * (pymin + pymax);

        float dx = fabsf((cx - pcx) / bw);
        float dy = fabsf((cy - pcy) / bh);
        dx = logf(fmaxf(dx, 1e-3f));
        dy = logf(fmaxf(dy, 1e-3f));
        const float dw = logf(pw / bw);
        const float dh = logf(ph / bh);
        float pos[4] = {dx, dy, dw, dh};

        float acc[16];
#pragma unroll
        for (int g = 0; g < 16; g++) acc[g] = wb[g];
#pragma unroll
        for (int i = 0; i < 4; i++) {
            const float pv = 100.f * pos[i];
#pragma unroll
            for (int j = 0; j < 8; j++) {
                float s, c;
                __sincosf(pv * inv_em[j], &s, &c);
#pragma unroll
                for (int g = 0; g < 16; g++)
                    acc[g] += s * wg[g * 64 + i * 16 + j]
                            + c * wg[g * 64 + i * 16 + 8 + j];
            }
        }
#pragma unroll
        for (int g = 0; g < 16; g++)
            sm[g * 1024 + p] = L[base + (size_t)g * 1024 + p]
                             + logf(fmaxf(acc[g], 1e-6f));
    }
    __syncthreads();

    const int w = t >> 5, lane = t & 31;
#pragma unroll
    for (int ggi = 0; ggi < 2; ggi++) {
        const int g = w * 2 + ggi;
        float* row = sm + g * 1024;

        float mx = -1e30f;
#pragma unroll
        for (int i = 0; i < 32; i++) mx = fmaxf(mx, row[i * 32 + lane]);
#pragma unroll
        for (int o = 16; o > 0; o >>= 1)
            mx = fmaxf(mx, __shfl_xor_sync(0xFFFFFFFFu, mx, o));

        float s = 0.f;
#pragma unroll
        for (int i = 0; i < 32; i++) {
            float e = __expf(row[i * 32 + lane] - mx);
            row[i * 32 + lane] = e;
            s += e;
        }
#pragma unroll
        for (int o = 16; o > 0; o >>= 1)
            s += __shfl_xor_sync(0xFFFFFFFFu, s, o);
        const float inv = 1.f / s;

#pragma unroll
        for (int i = 0; i < 32; i++)
            L[base + (size_t)g * 1024 + i * 32 + lane] = row[i * 32 + lane] * inv;
    }
}

// ---------------- host ----------------------------------------------------
extern "C" void kernel_launch(void* const* d_in, const int* in_sizes, int n_in,
                              void* d_out, int out_size)
{
    const float* rois       = (const float*)d_in[0];
    const float* part_rois  = (const float*)d_in[1];
    const float* box_feats  = (const float*)d_in[2];
    const float* part_feats = (const float*)d_in[3];
    const float* Wg_w       = (const float*)d_in[4];
    const float* Wg_b       = (const float*)d_in[5];
    const float* Wq_w       = (const float*)d_in[6];
    const float* Wq_b       = (const float*)d_in[7];
    const float* Wk_w       = (const float*)d_in[8];
    const float* Wk_b       = (const float*)d_in[9];
    const float* conv_w     = (const float*)d_in[10];
    const float* conv_b     = (const float*)d_in[11];
    float* out = (float*)d_out;

    float *q, *k, *pw, *L;
    cudaGetSymbolAddress((void**)&q,  g_q);
    cudaGetSymbolAddress((void**)&k,  g_k);
    cudaGetSymbolAddress((void**)&pw, g_pw);
    cudaGetSymbolAddress((void**)&L,  g_L);

    const int SMG  = 2 * (2 * 128 * 80 + 2 * 128 * 80); // 81920
    const int SMG2 = 2 * (2 * 256 * 80 + 2 * 64 * 80);  // 102400
    const int SMP  = (16 * 1024 + 16 * 64 + 16) * 4;    // 69696
    static bool attr_done = false;
    if (!attr_done) {
        cudaFuncSetAttribute((void*)tgemm<128, 128, 4, 4>,
                             cudaFuncAttributeMaxDynamicSharedMemorySize, SMG);
        cudaFuncSetAttribute((void*)tgemm<256, 64, 8, 2>,
                             cudaFuncAttributeMaxDynamicSharedMemorySize, SMG2);
        cudaFuncSetAttribute((void*)fused_ps,
                             cudaFuncAttributeMaxDynamicSharedMemorySize, SMP);
        attr_done = true;
    }

    // q = box_feats @ Wq^T + Wq_b         M=2048 N=1024 K=1024
    tgemm<128, 128, 4, 4><<<dim3(8, 16, 1), 512, SMG>>>(
        box_feats, Wq_w, Wq_b, q, 1024, 1024, 1024, 1024,
        0, 0, 0, 0, 0, 0, 0, 1, 1.f);

    // k = part_feats @ Wk^T + Wk_b
    tgemm<128, 128, 4, 4><<<dim3(8, 16, 1), 512, SMG>>>(
        part_feats, Wk_w, Wk_b, k, 1024, 1024, 1024, 1024,
        0, 0, 0, 0, 0, 0, 0, 1, 1.f);

    // pwT = conv_w @ part_feats^T         M=1024 N=2048 K=1024  -> [GE, P]
    tgemm<128, 128, 4, 4><<<dim3(16, 8, 1), 512, SMG>>>(
        conv_w, part_feats, nullptr, pw, 1024, 1024, 1024, 2048,
        0, 0, 0, 0, 0, 0, 0, 1, 1.f);

    // att/16 into L: 32 batches (b,g): M=1024 N=1024 K=64
    tgemm<128, 128, 4, 4><<<dim3(8, 8, 32), 512, SMG>>>(
        q, k, nullptr, L, 64, 1024, 1024, 16384,
        1048576LL, 64LL, 1048576LL, 64LL,
        16777216LL, 1024LL, 0LL, 16, 1.f / 16.f);

    // L = softmax(L + log(att_weight)) fused
    fused_ps<<<dim3(1024, 2), 256, SMP>>>(rois, part_rois, Wg_w, Wg_b, L);

    // rel = sm @ pwT^T + conv_b: 32 batches: M=1024 N=64 K=1024
    tgemm<256, 64, 8, 2><<<dim3(1, 4, 32), 512, SMG2>>>(
        L, pw, conv_b, out, 1024, 16384, 2048, 1024,
        16777216LL, 1024LL, 1024LL, 131072LL,
        1048576LL, 64LL, 64LL, 16, 1.f);
}

// round 6
// speedup vs baseline: 5.1022x; 5.1022x over previous
#include <cuda_runtime.h>
#include <cuda_bf16.h>
#include <cstdint>
#include <math.h>

// ---------------- scratch -------------------------------------------------
__device__ float g_q [2048 * 1024];      // box_feats @ Wq^T  (and part@Wk in same buf? no: separate)
__device__ float g_k [2048 * 1024];      // part_feats @ Wk^T
__device__ float g_pw[1024 * 2048];      // pwT = conv_w @ part_feats^T  [GE, P]
__device__ float g_L [2048 * 16 * 1024]; // logits / softmax

// ---------------- helpers -------------------------------------------------
__device__ __forceinline__ uint32_t smem_u32(const void* p) {
    uint32_t a;
    asm("{ .reg .u64 t; cvta.to.shared.u64 t, %1; cvt.u32.u64 %0, t; }"
        : "=r"(a) : "l"(p));
    return a;
}
__device__ __forceinline__ uint32_t pack_bf(float lo, float hi) {
    uint32_t r;
    asm("cvt.rn.bf16x2.f32 %0, %1, %2;" : "=r"(r) : "f"(hi), "f"(lo));
    return r;
}
#define STS64(a, x, y) \
    asm volatile("st.shared.v2.b32 [%0], {%1, %2};" :: "r"(a), "r"(x), "r"(y) : "memory")

__device__ __forceinline__ void ldsm4(uint32_t* r, uint32_t addr) {
    asm volatile("ldmatrix.sync.aligned.m8n8.x4.shared.b16 {%0,%1,%2,%3}, [%4];"
        : "=r"(r[0]), "=r"(r[1]), "=r"(r[2]), "=r"(r[3]) : "r"(addr));
}
__device__ __forceinline__ void mma16816(float* d, const uint32_t* a, const uint32_t* b) {
    asm volatile(
        "mma.sync.aligned.m16n8k16.row.col.f32.bf16.bf16.f32 "
        "{%0,%1,%2,%3}, {%4,%5,%6,%7}, {%8,%9}, {%0,%1,%2,%3};"
        : "+f"(d[0]), "+f"(d[1]), "+f"(d[2]), "+f"(d[3])
        : "r"(a[0]), "r"(a[1]), "r"(a[2]), "r"(a[3]), "r"(b[0]), "r"(b[1]));
}

// ---------------- bf16-split tensor-core GEMM (R3-proven config) ----------
// C[m,n] = alpha * sum_k A[m,k]*B[n,k] + bias[n]  (fp32 in/out, ~fp32 precision)
// BM=128, BN in {64,128}, BK=32 fp32 per iter, 256 threads.
// SMEM rows 80B (32 bf16 + 16B pad) -> ldmatrix conflict-free.
template <int BN>
__global__ __launch_bounds__(256) void tgemm(
    const float* __restrict__ A, const float* __restrict__ B,
    const float* __restrict__ bias, float* __restrict__ C,
    int K, int lda, int ldb, int ldc,
    long long sA1, long long sA2, long long sB1, long long sB2,
    long long sC1, long long sC2, long long sBias1, long long sBias2,
    int ngroup, float alpha)
{
    constexpr int WGM = (BN == 128) ? 4 : 8;
    constexpr int WGN = (BN == 128) ? 2 : 1;
    constexpr int WTM = 128 / WGM;          // 32 or 16
    constexpr int WTN = BN / WGN;           // 64
    constexpr int MB  = WTM / 16;           // 2 or 1
    constexpr int NB  = WTN / 8;            // 8
    constexpr int NB2 = WTN / 16;           // 4
    constexpr int A_MAT = 128 * 80;
    constexpr int B_MAT = BN * 80;
    constexpr int BUFSZ = 2 * A_MAT + 2 * B_MAT;
    constexpr int NB4B = BN / 32;

    extern __shared__ char smem[];
    const uint32_t sb = smem_u32(smem);

    const int t = threadIdx.x;
    const int wid = t >> 5, lane = t & 31;
    const int wm = wid % WGM, wn = wid / WGM;

    const int z = blockIdx.z;
    const int bb = z / ngroup;
    const int gg = z - bb * ngroup;
    A += bb * sA1 + gg * sA2;
    B += bb * sB1 + gg * sB2;
    C += bb * sC1 + gg * sC2;
    if (bias) bias += bb * sBias1 + gg * sBias2;

    const int m0 = blockIdx.y * 128;
    const int n0 = blockIdx.x * BN;

    float4 pa[4];
    float4 pb[NB4B];

    auto ldgA = [&](int c) {
        const int k0 = c * 32;
#pragma unroll
        for (int r = 0; r < 4; r++) {
            int f = r * 256 + t, row = f >> 3, seg = f & 7;
            pa[r] = *(const float4*)(A + (size_t)(m0 + row) * lda + k0 + seg * 4);
        }
    };
    auto ldgB = [&](int c) {
        const int k0 = c * 32;
#pragma unroll
        for (int r = 0; r < NB4B; r++) {
            int f = r * 256 + t, row = f >> 3, seg = f & 7;
            pb[r] = *(const float4*)(B + (size_t)(n0 + row) * ldb + k0 + seg * 4);
        }
    };
    auto sts = [&](int buf) {
        const uint32_t base = sb + buf * BUFSZ;
#pragma unroll
        for (int r = 0; r < 4; r++) {
            int f = r * 256 + t, row = f >> 3, seg = f & 7;
            float4 v = pa[r];
            uint32_t h01 = pack_bf(v.x, v.y);
            uint32_t h23 = pack_bf(v.z, v.w);
            float hx = __uint_as_float(h01 << 16);
            float hy = __uint_as_float(h01 & 0xFFFF0000u);
            float hz = __uint_as_float(h23 << 16);
            float hw = __uint_as_float(h23 & 0xFFFF0000u);
            uint32_t l01 = pack_bf(v.x - hx, v.y - hy);
            uint32_t l23 = pack_bf(v.z - hz, v.w - hw);
            uint32_t off = base + row * 80 + seg * 8;
            STS64(off, h01, h23);
            STS64(off + A_MAT, l01, l23);
        }
#pragma unroll
        for (int r = 0; r < NB4B; r++) {
            int f = r * 256 + t, row = f >> 3, seg = f & 7;
            float4 v = pb[r];
            uint32_t h01 = pack_bf(v.x, v.y);
            uint32_t h23 = pack_bf(v.z, v.w);
            float hx = __uint_as_float(h01 << 16);
            float hy = __uint_as_float(h01 & 0xFFFF0000u);
            float hz = __uint_as_float(h23 << 16);
            float hw = __uint_as_float(h23 & 0xFFFF0000u);
            uint32_t l01 = pack_bf(v.x - hx, v.y - hy);
            uint32_t l23 = pack_bf(v.z - hz, v.w - hw);
            uint32_t off = base + 2 * A_MAT + row * 80 + seg * 8;
            STS64(off, h01, h23);
            STS64(off + B_MAT, l01, l23);
        }
    };

    float acc[MB][NB][4];
#pragma unroll
    for (int i = 0; i < MB; i++)
#pragma unroll
        for (int j = 0; j < NB; j++)
#pragma unroll
            for (int q = 0; q < 4; q++) acc[i][j][q] = 0.f;

    const uint32_t a_lane = (uint32_t)((lane & 15) * 80 + (lane >> 4) * 16);
    const uint32_t b_lane = (uint32_t)(((lane & 7) + ((lane >> 4) << 3)) * 80
                                       + ((lane >> 3) & 1) * 16);

    auto compute = [&](int buf) {
        const uint32_t base = sb + buf * BUFSZ;
#pragma unroll
        for (int ks = 0; ks < 2; ks++) {
            const uint32_t ko = ks * 32;
            uint32_t Ah[MB][4], Al[MB][4], Bh[NB][2], Bl[NB][2];
#pragma unroll
            for (int mb = 0; mb < MB; mb++) {
                uint32_t ad = base + (wm * WTM + mb * 16) * 80 + a_lane + ko;
                ldsm4(Ah[mb], ad);
                ldsm4(Al[mb], ad + A_MAT);
            }
#pragma unroll
            for (int n2 = 0; n2 < NB2; n2++) {
                uint32_t bd = base + 2 * A_MAT + (wn * WTN + n2 * 16) * 80 + b_lane + ko;
                ldsm4(&Bh[2 * n2][0], bd);
                ldsm4(&Bl[2 * n2][0], bd + B_MAT);
            }
#pragma unroll
            for (int mb = 0; mb < MB; mb++)
#pragma unroll
                for (int nb = 0; nb < NB; nb++) {
                    mma16816(acc[mb][nb], Ah[mb], Bh[nb]);
                    mma16816(acc[mb][nb], Ah[mb], Bl[nb]);
                    mma16816(acc[mb][nb], Al[mb], Bh[nb]);
                }
        }
    };

    const int NC = K >> 5;
    ldgA(0); ldgB(0);
    sts(0);
    if (NC > 1) { ldgA(1); ldgB(1); }
    __syncthreads();

    for (int c = 0; c < NC; c++) {
        compute(c & 1);
        __syncthreads();
        if (c + 1 < NC) {
            sts((c + 1) & 1);
            __syncthreads();
            if (c + 2 < NC) { ldgA(c + 2); ldgB(c + 2); }
        }
    }

    // epilogue
    const int er = lane >> 2, ec = (lane & 3) * 2;
#pragma unroll
    for (int mb = 0; mb < MB; mb++) {
#pragma unroll
        for (int nb = 0; nb < NB; nb++) {
            const int m = m0 + wm * WTM + mb * 16 + er;
            const int n = n0 + wn * WTN + nb * 8 + ec;
            float b0 = 0.f, b1 = 0.f;
            if (bias) { b0 = bias[n]; b1 = bias[n + 1]; }
            float2 v0, v1;
            v0.x = alpha * acc[mb][nb][0] + b0;
            v0.y = alpha * acc[mb][nb][1] + b1;
            v1.x = alpha * acc[mb][nb][2] + b0;
            v1.y = alpha * acc[mb][nb][3] + b1;
            *(float2*)(C + (size_t)m * ldc + n) = v0;
            *(float2*)(C + (size_t)(m + 8) * ldc + n) = v1;
        }
    }
}

// ---------------- position embedding -> Wg -> log, added into L -----------
__global__ __launch_bounds__(256) void poslogit_kernel(
    const float* __restrict__ rois, const float* __restrict__ part_rois,
    const float* __restrict__ Wg_w, const float* __restrict__ Wg_b,
    float* __restrict__ L)
{
    __shared__ float wg[16][64];
    __shared__ float wb[16];
    const int t = threadIdx.x;
    for (int i = t; i < 1024; i += 256) wg[i >> 6][i & 63] = Wg_w[i];
    if (t < 16) wb[t] = Wg_b[t];

    const int b = blockIdx.z;
    const int n = blockIdx.y;
    const int p = blockIdx.x * 256 + t;
    const int ng = b * 1024 + n;
    const int pg = b * 1024 + p;

    const float xmin = rois[ng * 5 + 1];
    const float ymin = rois[ng * 5 + 2];
    const float xmax = rois[ng * 5 + 3];
    const float ymax = rois[ng * 5 + 4];
    const float pxmin = part_rois[pg * 5 + 1];
    const float pymin = part_rois[pg * 5 + 2];
    const float pxmax = part_rois[pg * 5 + 3];
    const float pymax = part_rois[pg * 5 + 4];
    __syncthreads();

    const float bw = xmax - xmin + 1.f;
    const float bh = ymax - ymin + 1.f;
    const float pw = pxmax - pxmin + 1.f;
    const float ph = pymax - pymin + 1.f;
    const float cx = 0.5f * (xmin + xmax);
    const float cy = 0.5f * (ymin + ymax);
    const float pcx = 0.5f * (pxmin + pxmax);
    const float pcy = 0.5f * (pymin + pymax);

    float dx = fabsf((cx - pcx) / bw);
    float dy = fabsf((cy - pcy) / bh);
    dx = logf(fmaxf(dx, 1e-3f));
    dy = logf(fmaxf(dy, 1e-3f));
    const float dw = logf(pw / bw);
    const float dh = logf(ph / bh);
    float pos[4] = {dx, dy, dw, dh};

    const float inv_em[8] = {
        1.0f, 0.42169651f, 0.17782794f, 0.074989424f,
        0.031622777f, 0.013335215f, 0.0056234133f, 0.0023713737f};

    float acc[16];
#pragma unroll
    for (int g = 0; g < 16; g++) acc[g] = wb[g];

#pragma unroll
    for (int i = 0; i < 4; i++) {
        const float pv = 100.f * pos[i];
#pragma unroll
        for (int j = 0; j < 8; j++) {
            float s, c;
            __sincosf(pv * inv_em[j], &s, &c);
#pragma unroll
            for (int g = 0; g < 16; g++)
                acc[g] += s * wg[g][i * 16 + j] + c * wg[g][i * 16 + 8 + j];
        }
    }

    size_t base = ((size_t)ng * 16) * 1024 + p;
#pragma unroll
    for (int g = 0; g < 16; g++) {
        float lw = logf(fmaxf(acc[g], 1e-6f));
        L[base + (size_t)g * 1024] += lw;
    }
}

// ---------------- row softmax over p (1024 per row), float4 ---------------
__global__ __launch_bounds__(256) void softmax_kernel(float* __restrict__ L)
{
    __shared__ float red[8];
    const size_t base = (size_t)blockIdx.x * 1024;
    const int t = threadIdx.x;
    const int w = t >> 5, lane = t & 31;

    float4 v = *(float4*)(L + base + t * 4);

    float mx = fmaxf(fmaxf(v.x, v.y), fmaxf(v.z, v.w));
#pragma unroll
    for (int o = 16; o > 0; o >>= 1)
        mx = fmaxf(mx, __shfl_xor_sync(0xFFFFFFFFu, mx, o));
    if (lane == 0) red[w] = mx;
    __syncthreads();
    mx = red[0];
#pragma unroll
    for (int i = 1; i < 8; i++) mx = fmaxf(mx, red[i]);

    v.x = __expf(v.x - mx);
    v.y = __expf(v.y - mx);
    v.z = __expf(v.z - mx);
    v.w = __expf(v.w - mx);
    float s = v.x + v.y + v.z + v.w;
#pragma unroll
    for (int o = 16; o > 0; o >>= 1)
        s += __shfl_xor_sync(0xFFFFFFFFu, s, o);
    __syncthreads();
    if (lane == 0) red[w] = s;
    __syncthreads();
    s = 0.f;
#pragma unroll
    for (int i = 0; i < 8; i++) s += red[i];
    const float inv = 1.f / s;

    v.x *= inv; v.y *= inv; v.z *= inv; v.w *= inv;
    *(float4*)(L + base + t * 4) = v;
}

// ---------------- host ----------------------------------------------------
extern "C" void kernel_launch(void* const* d_in, const int* in_sizes, int n_in,
                              void* d_out, int out_size)
{
    const float* rois       = (const float*)d_in[0];
    const float* part_rois  = (const float*)d_in[1];
    const float* box_feats  = (const float*)d_in[2];
    const float* part_feats = (const float*)d_in[3];
    const float* Wg_w       = (const float*)d_in[4];
    const float* Wg_b       = (const float*)d_in[5];
    const float* Wq_w       = (const float*)d_in[6];
    const float* Wq_b       = (const float*)d_in[7];
    const float* Wk_w       = (const float*)d_in[8];
    const float* Wk_b       = (const float*)d_in[9];
    const float* conv_w     = (const float*)d_in[10];
    const float* conv_b     = (const float*)d_in[11];
    float* out = (float*)d_out;

    float *q, *k, *pw, *L;
    cudaGetSymbolAddress((void**)&q,  g_q);
    cudaGetSymbolAddress((void**)&k,  g_k);
    cudaGetSymbolAddress((void**)&pw, g_pw);
    cudaGetSymbolAddress((void**)&L,  g_L);

    const int SM128 = 2 * (2 * 128 * 80 + 2 * 128 * 80); // 81920
    const int SM64  = 2 * (2 * 128 * 80 + 2 * 64 * 80);  // 61440
    cudaFuncSetAttribute(tgemm<128>, cudaFuncAttributeMaxDynamicSharedMemorySize, SM128);
    cudaFuncSetAttribute(tgemm<64>,  cudaFuncAttributeMaxDynamicSharedMemorySize, SM64);

    // merged q & k:  batch 0: q = box_feats @ Wq^T + Wq_b
    //                batch 1: k = part_feats @ Wk^T + Wk_b
    // batch strides are pointer differences between the input buffers.
    {
        long long dA = (long long)(part_feats - box_feats);
        long long dB = (long long)(Wk_w - Wq_w);
        long long dBias = (long long)(Wk_b - Wq_b);
        long long dC = (long long)(k - q);
        tgemm<128><<<dim3(8, 16, 2), 256, SM128>>>(
            box_feats, Wq_w, Wq_b, q, 1024, 1024, 1024, 1024,
            dA, 0, dB, 0, dC, 0, dBias, 0, 1, 1.f);
    }

    // pwT = conv_w @ part_feats^T         M=1024 N=2048 K=1024  -> [GE, P]
    tgemm<128><<<dim3(16, 8, 1), 256, SM128>>>(
        conv_w, part_feats, nullptr, pw, 1024, 1024, 1024, 2048,
        0, 0, 0, 0, 0, 0, 0, 0, 1, 1.f);

    // att/16 into L: 32 batches (b,g): M=1024 N=1024 K=64
    tgemm<128><<<dim3(8, 8, 32), 256, SM128>>>(
        q, k, nullptr, L, 64, 1024, 1024, 16384,
        1048576LL, 64LL, 1048576LL, 64LL,
        16777216LL, 1024LL, 0LL, 0LL, 16, 1.f / 16.f);

    // L += log(att_weight)
    poslogit_kernel<<<dim3(4, 1024, 2), 256>>>(rois, part_rois, Wg_w, Wg_b, L);

    // softmax over p (32768 rows of 1024)
    softmax_kernel<<<32768, 256>>>(L);

    // rel = sm @ pwT^T + conv_b: 32 batches: M=1024 N=64 K=1024
    tgemm<64><<<dim3(1, 8, 32), 256, SM64>>>(
        L, pw, conv_b, out, 1024, 16384, 2048, 1024,
        16777216LL, 1024LL, 1024LL, 131072LL,
        1048576LL, 64LL, 0LL, 64LL, 16, 1.f);
}

// round 8
// speedup vs baseline: 6.7882x; 1.3304x over previous
#include <cuda_runtime.h>
#include <cuda_bf16.h>
#include <cstdint>
#include <math.h>

// ---------------- scratch -------------------------------------------------
__device__ float g_q [2048 * 1024];      // box_feats @ Wq^T
__device__ float g_k [2048 * 1024];      // part_feats @ Wk^T
__device__ float g_pw[1024 * 2048];      // pwT = conv_w @ part_feats^T  [GE, P]
__device__ float g_L [2048 * 16 * 1024]; // logits / softmax

// ---------------- helpers -------------------------------------------------
__device__ __forceinline__ uint32_t smem_u32(const void* p) {
    uint32_t a;
    asm("{ .reg .u64 t; cvta.to.shared.u64 t, %1; cvt.u32.u64 %0, t; }"
        : "=r"(a) : "l"(p));
    return a;
}
__device__ __forceinline__ uint32_t pack_bf(float lo, float hi) {
    uint32_t r;
    asm("cvt.rn.bf16x2.f32 %0, %1, %2;" : "=r"(r) : "f"(hi), "f"(lo));
    return r;
}
#define STS64(a, x, y) \
    asm volatile("st.shared.v2.b32 [%0], {%1, %2};" :: "r"(a), "r"(x), "r"(y) : "memory")

__device__ __forceinline__ void ldsm4(uint32_t* r, uint32_t addr) {
    asm volatile("ldmatrix.sync.aligned.m8n8.x4.shared.b16 {%0,%1,%2,%3}, [%4];"
        : "=r"(r[0]), "=r"(r[1]), "=r"(r[2]), "=r"(r[3]) : "r"(addr));
}
__device__ __forceinline__ void mma16816(float* d, const uint32_t* a, const uint32_t* b) {
    asm volatile(
        "mma.sync.aligned.m16n8k16.row.col.f32.bf16.bf16.f32 "
        "{%0,%1,%2,%3}, {%4,%5,%6,%7}, {%8,%9}, {%0,%1,%2,%3};"
        : "+f"(d[0]), "+f"(d[1]), "+f"(d[2]), "+f"(d[3])
        : "r"(a[0]), "r"(a[1]), "r"(a[2]), "r"(a[3]), "r"(b[0]), "r"(b[1]));
}
// packed fp32x2 ops (sm_100+)
__device__ __forceinline__ void ffma2(unsigned long long& d,
                                      unsigned long long a, unsigned long long b) {
    asm("fma.rn.f32x2 %0, %1, %2, %0;" : "+l"(d) : "l"(a), "l"(b));
}
__device__ __forceinline__ unsigned long long pack2(float x, float y) {
    unsigned long long r;
    asm("mov.b64 %0, {%1, %2};" : "=l"(r) : "f"(x), "f"(y));
    return r;
}
__device__ __forceinline__ void unpack2(unsigned long long v, float& x, float& y) {
    asm("mov.b64 {%0, %1}, %2;" : "=f"(x), "=f"(y) : "l"(v));
}

// ---------------- bf16-split tensor-core GEMM (R3-proven config) ----------
template <int BN>
__global__ __launch_bounds__(256) void tgemm(
    const float* __restrict__ A, const float* __restrict__ B,
    const float* __restrict__ bias, float* __restrict__ C,
    int K, int lda, int ldb, int ldc,
    long long sA1, long long sA2, long long sB1, long long sB2,
    long long sC1, long long sC2, long long sBias1, long long sBias2,
    int ngroup, float alpha)
{
    constexpr int WGM = (BN == 128) ? 4 : 8;
    constexpr int WGN = (BN == 128) ? 2 : 1;
    constexpr int WTM = 128 / WGM;
    constexpr int WTN = BN / WGN;
    constexpr int MB  = WTM / 16;
    constexpr int NB  = WTN / 8;
    constexpr int NB2 = WTN / 16;
    constexpr int A_MAT = 128 * 80;
    constexpr int B_MAT = BN * 80;
    constexpr int BUFSZ = 2 * A_MAT + 2 * B_MAT;
    constexpr int NB4B = BN / 32;

    extern __shared__ char smem[];
    const uint32_t sb = smem_u32(smem);

    const int t = threadIdx.x;
    const int wid = t >> 5, lane = t & 31;
    const int wm = wid % WGM, wn = wid / WGM;

    const int z = blockIdx.z;
    const int bb = z / ngroup;
    const int gg = z - bb * ngroup;
    A += bb * sA1 + gg * sA2;
    B += bb * sB1 + gg * sB2;
    C += bb * sC1 + gg * sC2;
    if (bias) bias += bb * sBias1 + gg * sBias2;

    const int m0 = blockIdx.y * 128;
    const int n0 = blockIdx.x * BN;

    float4 pa[4];
    float4 pb[NB4B];

    auto ldgA = [&](int c) {
        const int k0 = c * 32;
#pragma unroll
        for (int r = 0; r < 4; r++) {
            int f = r * 256 + t, row = f >> 3, seg = f & 7;
            pa[r] = *(const float4*)(A + (size_t)(m0 + row) * lda + k0 + seg * 4);
        }
    };
    auto ldgB = [&](int c) {
        const int k0 = c * 32;
#pragma unroll
        for (int r = 0; r < NB4B; r++) {
            int f = r * 256 + t, row = f >> 3, seg = f & 7;
            pb[r] = *(const float4*)(B + (size_t)(n0 + row) * ldb + k0 + seg * 4);
        }
    };
    auto sts = [&](int buf) {
        const uint32_t base = sb + buf * BUFSZ;
#pragma unroll
        for (int r = 0; r < 4; r++) {
            int f = r * 256 + t, row = f >> 3, seg = f & 7;
            float4 v = pa[r];
            uint32_t h01 = pack_bf(v.x, v.y);
            uint32_t h23 = pack_bf(v.z, v.w);
            float hx = __uint_as_float(h01 << 16);
            float hy = __uint_as_float(h01 & 0xFFFF0000u);
            float hz = __uint_as_float(h23 << 16);
            float hw = __uint_as_float(h23 & 0xFFFF0000u);
            uint32_t l01 = pack_bf(v.x - hx, v.y - hy);
            uint32_t l23 = pack_bf(v.z - hz, v.w - hw);
            uint32_t off = base + row * 80 + seg * 8;
            STS64(off, h01, h23);
            STS64(off + A_MAT, l01, l23);
        }
#pragma unroll
        for (int r = 0; r < NB4B; r++) {
            int f = r * 256 + t, row = f >> 3, seg = f & 7;
            float4 v = pb[r];
            uint32_t h01 = pack_bf(v.x, v.y);
            uint32_t h23 = pack_bf(v.z, v.w);
            float hx = __uint_as_float(h01 << 16);
            float hy = __uint_as_float(h01 & 0xFFFF0000u);
            float hz = __uint_as_float(h23 << 16);
            float hw = __uint_as_float(h23 & 0xFFFF0000u);
            uint32_t l01 = pack_bf(v.x - hx, v.y - hy);
            uint32_t l23 = pack_bf(v.z - hz, v.w - hw);
            uint32_t off = base + 2 * A_MAT + row * 80 + seg * 8;
            STS64(off, h01, h23);
            STS64(off + B_MAT, l01, l23);
        }
    };

    float acc[MB][NB][4];
#pragma unroll
    for (int i = 0; i < MB; i++)
#pragma unroll
        for (int j = 0; j < NB; j++)
#pragma unroll
            for (int q = 0; q < 4; q++) acc[i][j][q] = 0.f;

    const uint32_t a_lane = (uint32_t)((lane & 15) * 80 + (lane >> 4) * 16);
    const uint32_t b_lane = (uint32_t)(((lane & 7) + ((lane >> 4) << 3)) * 80
                                       + ((lane >> 3) & 1) * 16);

    auto compute = [&](int buf) {
        const uint32_t base = sb + buf * BUFSZ;
#pragma unroll
        for (int ks = 0; ks < 2; ks++) {
            const uint32_t ko = ks * 32;
            uint32_t Ah[MB][4], Al[MB][4], Bh[NB][2], Bl[NB][2];
#pragma unroll
            for (int mb = 0; mb < MB; mb++) {
                uint32_t ad = base + (wm * WTM + mb * 16) * 80 + a_lane + ko;
                ldsm4(Ah[mb], ad);
                ldsm4(Al[mb], ad + A_MAT);
            }
#pragma unroll
            for (int n2 = 0; n2 < NB2; n2++) {
                uint32_t bd = base + 2 * A_MAT + (wn * WTN + n2 * 16) * 80 + b_lane + ko;
                ldsm4(&Bh[2 * n2][0], bd);
                ldsm4(&Bl[2 * n2][0], bd + B_MAT);
            }
#pragma unroll
            for (int mb = 0; mb < MB; mb++)
#pragma unroll
                for (int nb = 0; nb < NB; nb++) {
                    mma16816(acc[mb][nb], Ah[mb], Bh[nb]);
                    mma16816(acc[mb][nb], Ah[mb], Bl[nb]);
                    mma16816(acc[mb][nb], Al[mb], Bh[nb]);
                }
        }
    };

    const int NC = K >> 5;
    ldgA(0); ldgB(0);
    sts(0);
    if (NC > 1) { ldgA(1); ldgB(1); }
    __syncthreads();

    for (int c = 0; c < NC; c++) {
        compute(c & 1);
        __syncthreads();
        if (c + 1 < NC) {
            sts((c + 1) & 1);
            __syncthreads();
            if (c + 2 < NC) { ldgA(c + 2); ldgB(c + 2); }
        }
    }

    const int er = lane >> 2, ec = (lane & 3) * 2;
#pragma unroll
    for (int mb = 0; mb < MB; mb++) {
#pragma unroll
        for (int nb = 0; nb < NB; nb++) {
            const int m = m0 + wm * WTM + mb * 16 + er;
            const int n = n0 + wn * WTN + nb * 8 + ec;
            float b0 = 0.f, b1 = 0.f;
            if (bias) { b0 = bias[n]; b1 = bias[n + 1]; }
            float2 v0, v1;
            v0.x = alpha * acc[mb][nb][0] + b0;
            v0.y = alpha * acc[mb][nb][1] + b1;
            v1.x = alpha * acc[mb][nb][2] + b0;
            v1.y = alpha * acc[mb][nb][3] + b1;
            *(float2*)(C + (size_t)m * ldc + n) = v0;
            *(float2*)(C + (size_t)(m + 8) * ldc + n) = v1;
        }
    }
}

// ---------------- position embedding -> Wg -> log, added into L -----------
// packed f32x2 accumulation over group pairs; Wg pre-packed in smem.
__global__ __launch_bounds__(256) void poslogit_kernel(
    const float* __restrict__ rois, const float* __restrict__ part_rois,
    const float* __restrict__ Wg_w, const float* __restrict__ Wg_b,
    float* __restrict__ L)
{
    // wgp[(i*8+j)*8 + g2] = { pack2(wgS[2g2], wgS[2g2+1]), pack2(wgC[2g2], wgC[2g2+1]) }
    // where wgS = Wg_w[g][i*16+j], wgC = Wg_w[g][i*16+8+j]
    __shared__ ulonglong2 wgp[256];
    __shared__ unsigned long long wbp[8];

    const int t = threadIdx.x;
    {
        const int g2 = t & 7, j = (t >> 3) & 7, i = t >> 6;
        const int r0 = (2 * g2) * 64, r1 = (2 * g2 + 1) * 64;
        ulonglong2 w;
        w.x = pack2(Wg_w[r0 + i * 16 + j],     Wg_w[r1 + i * 16 + j]);
        w.y = pack2(Wg_w[r0 + i * 16 + 8 + j], Wg_w[r1 + i * 16 + 8 + j]);
        wgp[t] = w;
        if (t < 8) wbp[t] = pack2(Wg_b[2 * t], Wg_b[2 * t + 1]);
    }

    const int b = blockIdx.z;
    const int n = blockIdx.y;
    const int p = blockIdx.x * 256 + t;
    const int ng = b * 1024 + n;
    const int pg = b * 1024 + p;

    const float xmin = rois[ng * 5 + 1];
    const float ymin = rois[ng * 5 + 2];
    const float xmax = rois[ng * 5 + 3];
    const float ymax = rois[ng * 5 + 4];
    const float pxmin = part_rois[pg * 5 + 1];
    const float pymin = part_rois[pg * 5 + 2];
    const float pxmax = part_rois[pg * 5 + 3];
    const float pymax = part_rois[pg * 5 + 4];
    __syncthreads();

    const float bw = xmax - xmin + 1.f;
    const float bh = ymax - ymin + 1.f;
    const float pw = pxmax - pxmin + 1.f;
    const float ph = pymax - pymin + 1.f;
    const float cx = 0.5f * (xmin + xmax);
    const float cy = 0.5f * (ymin + ymax);
    const float pcx = 0.5f * (pxmin + pxmax);
    const float pcy = 0.5f * (pymin + pymax);

    float dx = fabsf((cx - pcx) / bw);
    float dy = fabsf((cy - pcy) / bh);
    dx = __logf(fmaxf(dx, 1e-3f));
    dy = __logf(fmaxf(dy, 1e-3f));
    const float dw = __logf(pw / bw);
    const float dh = __logf(ph / bh);
    float pos[4] = {dx, dy, dw, dh};

    const float inv_em[8] = {
        1.0f, 0.42169651f, 0.17782794f, 0.074989424f,
        0.031622777f, 0.013335215f, 0.0056234133f, 0.0023713737f};

    unsigned long long acc2[8];
#pragma unroll
    for (int g2 = 0; g2 < 8; g2++) acc2[g2] = wbp[g2];

#pragma unroll
    for (int i = 0; i < 4; i++) {
        const float pv = 100.f * pos[i];
#pragma unroll
        for (int j = 0; j < 8; j++) {
            float s, c;
            __sincosf(pv * inv_em[j], &s, &c);
            const unsigned long long s2 = pack2(s, s);
            const unsigned long long c2 = pack2(c, c);
            const ulonglong2* wrow = &wgp[(i * 8 + j) * 8];
#pragma unroll
            for (int g2 = 0; g2 < 8; g2++) {
                ulonglong2 w = wrow[g2];
                ffma2(acc2[g2], s2, w.x);
                ffma2(acc2[g2], c2, w.y);
            }
        }
    }

    size_t base = ((size_t)ng * 16) * 1024 + p;
#pragma unroll
    for (int g2 = 0; g2 < 8; g2++) {
        float a0, a1;
        unpack2(acc2[g2], a0, a1);
        L[base + (size_t)(2 * g2) * 1024]     += __logf(fmaxf(a0, 1e-6f));
        L[base + (size_t)(2 * g2 + 1) * 1024] += __logf(fmaxf(a1, 1e-6f));
    }
}

// ---------------- row softmax over p (1024 per row), float4 ---------------
__global__ __launch_bounds__(256) void softmax_kernel(float* __restrict__ L)
{
    __shared__ float red[8];
    const size_t base = (size_t)blockIdx.x * 1024;
    const int t = threadIdx.x;
    const int w = t >> 5, lane = t & 31;

    float4 v = *(float4*)(L + base + t * 4);

    float mx = fmaxf(fmaxf(v.x, v.y), fmaxf(v.z, v.w));
#pragma unroll
    for (int o = 16; o > 0; o >>= 1)
        mx = fmaxf(mx, __shfl_xor_sync(0xFFFFFFFFu, mx, o));
    if (lane == 0) red[w] = mx;
    __syncthreads();
    mx = red[0];
#pragma unroll
    for (int i = 1; i < 8; i++) mx = fmaxf(mx, red[i]);

    v.x = __expf(v.x - mx);
    v.y = __expf(v.y - mx);
    v.z = __expf(v.z - mx);
    v.w = __expf(v.w - mx);
    float s = v.x + v.y + v.z + v.w;
#pragma unroll
    for (int o = 16; o > 0; o >>= 1)
        s += __shfl_xor_sync(0xFFFFFFFFu, s, o);
    __syncthreads();
    if (lane == 0) red[w] = s;
    __syncthreads();
    s = 0.f;
#pragma unroll
    for (int i = 0; i < 8; i++) s += red[i];
    const float inv = 1.f / s;

    v.x *= inv; v.y *= inv; v.z *= inv; v.w *= inv;
    *(float4*)(L + base + t * 4) = v;
}

// ---------------- host ----------------------------------------------------
extern "C" void kernel_launch(void* const* d_in, const int* in_sizes, int n_in,
                              void* d_out, int out_size)
{
    const float* rois       = (const float*)d_in[0];
    const float* part_rois  = (const float*)d_in[1];
    const float* box_feats  = (const float*)d_in[2];
    const float* part_feats = (const float*)d_in[3];
    const float* Wg_w       = (const float*)d_in[4];
    const float* Wg_b       = (const float*)d_in[5];
    const float* Wq_w       = (const float*)d_in[6];
    const float* Wq_b       = (const float*)d_in[7];
    const float* Wk_w       = (const float*)d_in[8];
    const float* Wk_b       = (const float*)d_in[9];
    const float* conv_w     = (const float*)d_in[10];
    const float* conv_b     = (const float*)d_in[11];
    float* out = (float*)d_out;

    float *q, *k, *pw, *L;
    cudaGetSymbolAddress((void**)&q,  g_q);
    cudaGetSymbolAddress((void**)&k,  g_k);
    cudaGetSymbolAddress((void**)&pw, g_pw);
    cudaGetSymbolAddress((void**)&L,  g_L);

    const int SM128 = 2 * (2 * 128 * 80 + 2 * 128 * 80); // 81920
    const int SM64  = 2 * (2 * 128 * 80 + 2 * 64 * 80);  // 61440
    cudaFuncSetAttribute(tgemm<128>, cudaFuncAttributeMaxDynamicSharedMemorySize, SM128);
    cudaFuncSetAttribute(tgemm<64>,  cudaFuncAttributeMaxDynamicSharedMemorySize, SM64);

    // merged q & k projections via pointer-difference batch strides
    {
        long long dA = (long long)(part_feats - box_feats);
        long long dB = (long long)(Wk_w - Wq_w);
        long long dBias = (long long)(Wk_b - Wq_b);
        long long dC = (long long)(k - q);
        tgemm<128><<<dim3(8, 16, 2), 256, SM128>>>(
            box_feats, Wq_w, Wq_b, q, 1024, 1024, 1024, 1024,
            dA, 0, dB, 0, dC, 0, dBias, 0, 1, 1.f);
    }

    // pwT = conv_w @ part_feats^T         M=1024 N=2048 K=1024  -> [GE, P]
    tgemm<128><<<dim3(16, 8, 1), 256, SM128>>>(
        conv_w, part_feats, nullptr, pw, 1024, 1024, 1024, 2048,
        0, 0, 0, 0, 0, 0, 0, 0, 1, 1.f);

    // att/16 into L: 32 batches (b,g): M=1024 N=1024 K=64
    tgemm<128><<<dim3(8, 8, 32), 256, SM128>>>(
        q, k, nullptr, L, 64, 1024, 1024, 16384,
        1048576LL, 64LL, 1048576LL, 64LL,
        16777216LL, 1024LL, 0LL, 0LL, 16, 1.f / 16.f);

    // L += log(att_weight)
    poslogit_kernel<<<dim3(4, 1024, 2), 256>>>(rois, part_rois, Wg_w, Wg_b, L);

    // softmax over p (32768 rows of 1024)
    softmax_kernel<<<32768, 256>>>(L);

    // rel = sm @ pwT^T + conv_b: 32 batches: M=1024 N=64 K=1024
    tgemm<64><<<dim3(1, 8, 32), 256, SM64>>>(
        L, pw, conv_b, out, 1024, 16384, 2048, 1024,
        16777216LL, 1024LL, 1024LL, 131072LL,
        1048576LL, 64LL, 0LL, 64LL, 16, 1.f);
}

// round 9
// speedup vs baseline: 7.4159x; 1.0925x over previous
#include <cuda_runtime.h>
#include <cuda_bf16.h>
#include <cstdint>
#include <math.h>

// ---------------- scratch -------------------------------------------------
__device__ float g_q [2048 * 1024];      // box_feats @ Wq^T
__device__ float g_k [2048 * 1024];      // part_feats @ Wk^T
__device__ float g_pw[1024 * 2048];      // pwT = conv_w @ part_feats^T  [GE, P]
__device__ float g_L [2048 * 16 * 1024]; // logits / softmax

// ---------------- helpers -------------------------------------------------
__device__ __forceinline__ uint32_t smem_u32(const void* p) {
    uint32_t a;
    asm("{ .reg .u64 t; cvta.to.shared.u64 t, %1; cvt.u32.u64 %0, t; }"
        : "=r"(a) : "l"(p));
    return a;
}
__device__ __forceinline__ uint32_t pack_bf(float lo, float hi) {
    uint32_t r;
    asm("cvt.rn.bf16x2.f32 %0, %1, %2;" : "=r"(r) : "f"(hi), "f"(lo));
    return r;
}
#define STS64(a, x, y) \
    asm volatile("st.shared.v2.b32 [%0], {%1, %2};" :: "r"(a), "r"(x), "r"(y) : "memory")

__device__ __forceinline__ void ldsm4(uint32_t* r, uint32_t addr) {
    asm volatile("ldmatrix.sync.aligned.m8n8.x4.shared.b16 {%0,%1,%2,%3}, [%4];"
        : "=r"(r[0]), "=r"(r[1]), "=r"(r[2]), "=r"(r[3]) : "r"(addr));
}
__device__ __forceinline__ void mma16816(float* d, const uint32_t* a, const uint32_t* b) {
    asm volatile(
        "mma.sync.aligned.m16n8k16.row.col.f32.bf16.bf16.f32 "
        "{%0,%1,%2,%3}, {%4,%5,%6,%7}, {%8,%9}, {%0,%1,%2,%3};"
        : "+f"(d[0]), "+f"(d[1]), "+f"(d[2]), "+f"(d[3])
        : "r"(a[0]), "r"(a[1]), "r"(a[2]), "r"(a[3]), "r"(b[0]), "r"(b[1]));
}
// packed fp32x2 ops (sm_100+)
__device__ __forceinline__ void ffma2(unsigned long long& d,
                                      unsigned long long a, unsigned long long b) {
    asm("fma.rn.f32x2 %0, %1, %2, %0;" : "+l"(d) : "l"(a), "l"(b));
}
__device__ __forceinline__ unsigned long long pack2(float x, float y) {
    unsigned long long r;
    asm("mov.b64 %0, {%1, %2};" : "=l"(r) : "f"(x), "f"(y));
    return r;
}
__device__ __forceinline__ void unpack2(unsigned long long v, float& x, float& y) {
    asm("mov.b64 {%0, %1}, %2;" : "=f"(x), "=f"(y) : "l"(v));
}

// ---------------- bf16-split tensor-core GEMM (R3-proven config) ----------
template <int BN>
__global__ __launch_bounds__(256) void tgemm(
    const float* __restrict__ A, const float* __restrict__ B,
    const float* __restrict__ bias, float* __restrict__ C,
    int K, int lda, int ldb, int ldc,
    long long sA1, long long sA2, long long sB1, long long sB2,
    long long sC1, long long sC2, long long sBias1, long long sBias2,
    int ngroup, float alpha)
{
    constexpr int WGM = (BN == 128) ? 4 : 8;
    constexpr int WGN = (BN == 128) ? 2 : 1;
    constexpr int WTM = 128 / WGM;
    constexpr int WTN = BN / WGN;
    constexpr int MB  = WTM / 16;
    constexpr int NB  = WTN / 8;
    constexpr int NB2 = WTN / 16;
    constexpr int A_MAT = 128 * 80;
    constexpr int B_MAT = BN * 80;
    constexpr int BUFSZ = 2 * A_MAT + 2 * B_MAT;
    constexpr int NB4B = BN / 32;

    extern __shared__ char smem[];
    const uint32_t sb = smem_u32(smem);

    const int t = threadIdx.x;
    const int wid = t >> 5, lane = t & 31;
    const int wm = wid % WGM, wn = wid / WGM;

    const int z = blockIdx.z;
    const int bb = z / ngroup;
    const int gg = z - bb * ngroup;
    A += bb * sA1 + gg * sA2;
    B += bb * sB1 + gg * sB2;
    C += bb * sC1 + gg * sC2;
    if (bias) bias += bb * sBias1 + gg * sBias2;

    const int m0 = blockIdx.y * 128;
    const int n0 = blockIdx.x * BN;

    float4 pa[4];
    float4 pb[NB4B];

    auto ldgA = [&](int c) {
        const int k0 = c * 32;
#pragma unroll
        for (int r = 0; r < 4; r++) {
            int f = r * 256 + t, row = f >> 3, seg = f & 7;
            pa[r] = *(const float4*)(A + (size_t)(m0 + row) * lda + k0 + seg * 4);
        }
    };
    auto ldgB = [&](int c) {
        const int k0 = c * 32;
#pragma unroll
        for (int r = 0; r < NB4B; r++) {
            int f = r * 256 + t, row = f >> 3, seg = f & 7;
            pb[r] = *(const float4*)(B + (size_t)(n0 + row) * ldb + k0 + seg * 4);
        }
    };
    auto sts = [&](int buf) {
        const uint32_t base = sb + buf * BUFSZ;
#pragma unroll
        for (int r = 0; r < 4; r++) {
            int f = r * 256 + t, row = f >> 3, seg = f & 7;
            float4 v = pa[r];
            uint32_t h01 = pack_bf(v.x, v.y);
            uint32_t h23 = pack_bf(v.z, v.w);
            float hx = __uint_as_float(h01 << 16);
            float hy = __uint_as_float(h01 & 0xFFFF0000u);
            float hz = __uint_as_float(h23 << 16);
            float hw = __uint_as_float(h23 & 0xFFFF0000u);
            uint32_t l01 = pack_bf(v.x - hx, v.y - hy);
            uint32_t l23 = pack_bf(v.z - hz, v.w - hw);
            uint32_t off = base + row * 80 + seg * 8;
            STS64(off, h01, h23);
            STS64(off + A_MAT, l01, l23);
        }
#pragma unroll
        for (int r = 0; r < NB4B; r++) {
            int f = r * 256 + t, row = f >> 3, seg = f & 7;
            float4 v = pb[r];
            uint32_t h01 = pack_bf(v.x, v.y);
            uint32_t h23 = pack_bf(v.z, v.w);
            float hx = __uint_as_float(h01 << 16);
            float hy = __uint_as_float(h01 & 0xFFFF0000u);
            float hz = __uint_as_float(h23 << 16);
            float hw = __uint_as_float(h23 & 0xFFFF0000u);
            uint32_t l01 = pack_bf(v.x - hx, v.y - hy);
            uint32_t l23 = pack_bf(v.z - hz, v.w - hw);
            uint32_t off = base + 2 * A_MAT + row * 80 + seg * 8;
            STS64(off, h01, h23);
            STS64(off + B_MAT, l01, l23);
        }
    };

    float acc[MB][NB][4];
#pragma unroll
    for (int i = 0; i < MB; i++)
#pragma unroll
        for (int j = 0; j < NB; j++)
#pragma unroll
            for (int q = 0; q < 4; q++) acc[i][j][q] = 0.f;

    const uint32_t a_lane = (uint32_t)((lane & 15) * 80 + (lane >> 4) * 16);
    const uint32_t b_lane = (uint32_t)(((lane & 7) + ((lane >> 4) << 3)) * 80
                                       + ((lane >> 3) & 1) * 16);

    auto compute = [&](int buf) {
        const uint32_t base = sb + buf * BUFSZ;
#pragma unroll
        for (int ks = 0; ks < 2; ks++) {
            const uint32_t ko = ks * 32;
            uint32_t Ah[MB][4], Al[MB][4], Bh[NB][2], Bl[NB][2];
#pragma unroll
            for (int mb = 0; mb < MB; mb++) {
                uint32_t ad = base + (wm * WTM + mb * 16) * 80 + a_lane + ko;
                ldsm4(Ah[mb], ad);
                ldsm4(Al[mb], ad + A_MAT);
            }
#pragma unroll
            for (int n2 = 0; n2 < NB2; n2++) {
                uint32_t bd = base + 2 * A_MAT + (wn * WTN + n2 * 16) * 80 + b_lane + ko;
                ldsm4(&Bh[2 * n2][0], bd);
                ldsm4(&Bl[2 * n2][0], bd + B_MAT);
            }
#pragma unroll
            for (int mb = 0; mb < MB; mb++)
#pragma unroll
                for (int nb = 0; nb < NB; nb++) {
                    mma16816(acc[mb][nb], Ah[mb], Bh[nb]);
                    mma16816(acc[mb][nb], Ah[mb], Bl[nb]);
                    mma16816(acc[mb][nb], Al[mb], Bh[nb]);
                }
        }
    };

    const int NC = K >> 5;
    ldgA(0); ldgB(0);
    sts(0);
    if (NC > 1) { ldgA(1); ldgB(1); }
    __syncthreads();

    for (int c = 0; c < NC; c++) {
        compute(c & 1);
        __syncthreads();
        if (c + 1 < NC) {
            sts((c + 1) & 1);
            __syncthreads();
            if (c + 2 < NC) { ldgA(c + 2); ldgB(c + 2); }
        }
    }

    const int er = lane >> 2, ec = (lane & 3) * 2;
#pragma unroll
    for (int mb = 0; mb < MB; mb++) {
#pragma unroll
        for (int nb = 0; nb < NB; nb++) {
            const int m = m0 + wm * WTM + mb * 16 + er;
            const int n = n0 + wn * WTN + nb * 8 + ec;
            float b0 = 0.f, b1 = 0.f;
            if (bias) { b0 = bias[n]; b1 = bias[n + 1]; }
            float2 v0, v1;
            v0.x = alpha * acc[mb][nb][0] + b0;
            v0.y = alpha * acc[mb][nb][1] + b1;
            v1.x = alpha * acc[mb][nb][2] + b0;
            v1.y = alpha * acc[mb][nb][3] + b1;
            *(float2*)(C + (size_t)m * ldc + n) = v0;
            *(float2*)(C + (size_t)(m + 8) * ldc + n) = v1;
        }
    }
}

// ---------------- position embedding -> Wg -> log, added into L -----------
// 4 parts per thread: weight LDS amortized 4x; packed f32x2 accumulation.
__global__ __launch_bounds__(256) void poslogit_kernel(
    const float* __restrict__ rois, const float* __restrict__ part_rois,
    const float* __restrict__ Wg_w, const float* __restrict__ Wg_b,
    float* __restrict__ L)
{
    // wgp[(i*8+j)*8 + g2] = { pack2(wgS[2g2], wgS[2g2+1]), pack2(wgC[2g2], wgC[2g2+1]) }
    __shared__ ulonglong2 wgp[256];
    __shared__ unsigned long long wbp[8];

    const int t = threadIdx.x;
    {
        const int g2 = t & 7, j = (t >> 3) & 7, i = t >> 6;
        const int r0 = (2 * g2) * 64, r1 = (2 * g2 + 1) * 64;
        ulonglong2 w;
        w.x = pack2(Wg_w[r0 + i * 16 + j],     Wg_w[r1 + i * 16 + j]);
        w.y = pack2(Wg_w[r0 + i * 16 + 8 + j], Wg_w[r1 + i * 16 + 8 + j]);
        wgp[t] = w;
        if (t < 8) wbp[t] = pack2(Wg_b[2 * t], Wg_b[2 * t + 1]);
    }

    const int n = blockIdx.x;
    const int b = blockIdx.y;
    const int ng = b * 1024 + n;

    const float xmin = rois[ng * 5 + 1];
    const float ymin = rois[ng * 5 + 2];
    const float xmax = rois[ng * 5 + 3];
    const float ymax = rois[ng * 5 + 4];
    const float bw = xmax - xmin + 1.f;
    const float bh = ymax - ymin + 1.f;
    const float cx = 0.5f * (xmin + xmax);
    const float cy = 0.5f * (ymin + ymax);

    float pos[4][4];
#pragma unroll
    for (int pp = 0; pp < 4; pp++) {
        const int pg = b * 1024 + pp * 256 + t;
        const float pxmin = part_rois[pg * 5 + 1];
        const float pymin = part_rois[pg * 5 + 2];
        const float pxmax = part_rois[pg * 5 + 3];
        const float pymax = part_rois[pg * 5 + 4];
        const float pw = pxmax - pxmin + 1.f;
        const float ph = pymax - pymin + 1.f;
        const float pcx = 0.5f * (pxmin + pxmax);
        const float pcy = 0.5f * (pymin + pymax);
        float dx = fabsf((cx - pcx) / bw);
        float dy = fabsf((cy - pcy) / bh);
        pos[pp][0] = __logf(fmaxf(dx, 1e-3f));
        pos[pp][1] = __logf(fmaxf(dy, 1e-3f));
        pos[pp][2] = __logf(pw / bw);
        pos[pp][3] = __logf(ph / bh);
    }
    __syncthreads();

    const float inv_em[8] = {
        1.0f, 0.42169651f, 0.17782794f, 0.074989424f,
        0.031622777f, 0.013335215f, 0.0056234133f, 0.0023713737f};

    unsigned long long acc2[4][8];
#pragma unroll
    for (int pp = 0; pp < 4; pp++)
#pragma unroll
        for (int g2 = 0; g2 < 8; g2++) acc2[pp][g2] = wbp[g2];

#pragma unroll
    for (int i = 0; i < 4; i++) {
#pragma unroll
        for (int j = 0; j < 8; j++) {
            unsigned long long s2[4], c2[4];
#pragma unroll
            for (int pp = 0; pp < 4; pp++) {
                float s, c;
                __sincosf(100.f * pos[pp][i] * inv_em[j], &s, &c);
                s2[pp] = pack2(s, s);
                c2[pp] = pack2(c, c);
            }
            const ulonglong2* wrow = &wgp[(i * 8 + j) * 8];
#pragma unroll
            for (int g2 = 0; g2 < 8; g2++) {
                ulonglong2 w = wrow[g2];
#pragma unroll
                for (int pp = 0; pp < 4; pp++) {
                    ffma2(acc2[pp][g2], s2[pp], w.x);
                    ffma2(acc2[pp][g2], c2[pp], w.y);
                }
            }
        }
    }

    const size_t base = ((size_t)ng * 16) * 1024 + t;
#pragma unroll
    for (int pp = 0; pp < 4; pp++) {
#pragma unroll
        for (int g2 = 0; g2 < 8; g2++) {
            float a0, a1;
            unpack2(acc2[pp][g2], a0, a1);
            L[base + (size_t)(2 * g2) * 1024 + pp * 256]     += __logf(fmaxf(a0, 1e-6f));
            L[base + (size_t)(2 * g2 + 1) * 1024 + pp * 256] += __logf(fmaxf(a1, 1e-6f));
        }
    }
}

// ---------------- row softmax over p (1024 per row), float4 ---------------
__global__ __launch_bounds__(256) void softmax_kernel(float* __restrict__ L)
{
    __shared__ float red[8];
    const size_t base = (size_t)blockIdx.x * 1024;
    const int t = threadIdx.x;
    const int w = t >> 5, lane = t & 31;

    float4 v = *(float4*)(L + base + t * 4);

    float mx = fmaxf(fmaxf(v.x, v.y), fmaxf(v.z, v.w));
#pragma unroll
    for (int o = 16; o > 0; o >>= 1)
        mx = fmaxf(mx, __shfl_xor_sync(0xFFFFFFFFu, mx, o));
    if (lane == 0) red[w] = mx;
    __syncthreads();
    mx = red[0];
#pragma unroll
    for (int i = 1; i < 8; i++) mx = fmaxf(mx, red[i]);

    v.x = __expf(v.x - mx);
    v.y = __expf(v.y - mx);
    v.z = __expf(v.z - mx);
    v.w = __expf(v.w - mx);
    float s = v.x + v.y + v.z + v.w;
#pragma unroll
    for (int o = 16; o > 0; o >>= 1)
        s += __shfl_xor_sync(0xFFFFFFFFu, s, o);
    __syncthreads();
    if (lane == 0) red[w] = s;
    __syncthreads();
    s = 0.f;
#pragma unroll
    for (int i = 0; i < 8; i++) s += red[i];
    const float inv = 1.f / s;

    v.x *= inv; v.y *= inv; v.z *= inv; v.w *= inv;
    *(float4*)(L + base + t * 4) = v;
}

// ---------------- host ----------------------------------------------------
extern "C" void kernel_launch(void* const* d_in, const int* in_sizes, int n_in,
                              void* d_out, int out_size)
{
    const float* rois       = (const float*)d_in[0];
    const float* part_rois  = (const float*)d_in[1];
    const float* box_feats  = (const float*)d_in[2];
    const float* part_feats = (const float*)d_in[3];
    const float* Wg_w       = (const float*)d_in[4];
    const float* Wg_b       = (const float*)d_in[5];
    const float* Wq_w       = (const float*)d_in[6];
    const float* Wq_b       = (const float*)d_in[7];
    const float* Wk_w       = (const float*)d_in[8];
    const float* Wk_b       = (const float*)d_in[9];
    const float* conv_w     = (const float*)d_in[10];
    const float* conv_b     = (const float*)d_in[11];
    float* out = (float*)d_out;

    float *q, *k, *pw, *L;
    cudaGetSymbolAddress((void**)&q,  g_q);
    cudaGetSymbolAddress((void**)&k,  g_k);
    cudaGetSymbolAddress((void**)&pw, g_pw);
    cudaGetSymbolAddress((void**)&L,  g_L);

    const int SM128 = 2 * (2 * 128 * 80 + 2 * 128 * 80); // 81920
    const int SM64  = 2 * (2 * 128 * 80 + 2 * 64 * 80);  // 61440
    cudaFuncSetAttribute(tgemm<128>, cudaFuncAttributeMaxDynamicSharedMemorySize, SM128);
    cudaFuncSetAttribute(tgemm<64>,  cudaFuncAttributeMaxDynamicSharedMemorySize, SM64);

    // merged q & k projections via pointer-difference batch strides
    {
        long long dA = (long long)(part_feats - box_feats);
        long long dB = (long long)(Wk_w - Wq_w);
        long long dBias = (long long)(Wk_b - Wq_b);
        long long dC = (long long)(k - q);
        tgemm<128><<<dim3(8, 16, 2), 256, SM128>>>(
            box_feats, Wq_w, Wq_b, q, 1024, 1024, 1024, 1024,
            dA, 0, dB, 0, dC, 0, dBias, 0, 1, 1.f);
    }

    // pwT = conv_w @ part_feats^T         M=1024 N=2048 K=1024  -> [GE, P]
    tgemm<128><<<dim3(16, 8, 1), 256, SM128>>>(
        conv_w, part_feats, nullptr, pw, 1024, 1024, 1024, 2048,
        0, 0, 0, 0, 0, 0, 0, 0, 1, 1.f);

    // att/16 into L: 32 batches (b,g): M=1024 N=1024 K=64
    tgemm<128><<<dim3(8, 8, 32), 256, SM128>>>(
        q, k, nullptr, L, 64, 1024, 1024, 16384,
        1048576LL, 64LL, 1048576LL, 64LL,
        16777216LL, 1024LL, 0LL, 0LL, 16, 1.f / 16.f);

    // L += log(att_weight)   (one block per (n,b), 4 parts per thread)
    poslogit_kernel<<<dim3(1024, 2), 256>>>(rois, part_rois, Wg_w, Wg_b, L);

    // softmax over p (32768 rows of 1024)
    softmax_kernel<<<32768, 256>>>(L);

    // rel = sm @ pwT^T + conv_b: 32 batches: M=1024 N=64 K=1024
    tgemm<64><<<dim3(1, 8, 32), 256, SM64>>>(
        L, pw, conv_b, out, 1024, 16384, 2048, 1024,
        16777216LL, 1024LL, 1024LL, 131072LL,
        1048576LL, 64LL, 0LL, 64LL, 16, 1.f);
}

// round 12
// speedup vs baseline: 7.6563x; 1.0324x over previous
#include <cuda_runtime.h>
#include <cuda_bf16.h>
#include <cstdint>
#include <math.h>

// ---------------- scratch -------------------------------------------------
__device__ float g_q [2048 * 1024];      // box_feats @ Wq^T
__device__ float g_k [2048 * 1024];      // part_feats @ Wk^T
__device__ float g_pw[1024 * 2048];      // pwT = conv_w @ part_feats^T  [GE, P]
__device__ float g_L [2048 * 16 * 1024]; // logits / softmax

// ---------------- helpers -------------------------------------------------
__device__ __forceinline__ uint32_t smem_u32(const void* p) {
    uint32_t a;
    asm("{ .reg .u64 t; cvta.to.shared.u64 t, %1; cvt.u32.u64 %0, t; }"
        : "=r"(a) : "l"(p));
    return a;
}
__device__ __forceinline__ uint32_t pack_bf(float lo, float hi) {
    uint32_t r;
    asm("cvt.rn.bf16x2.f32 %0, %1, %2;" : "=r"(r) : "f"(hi), "f"(lo));
    return r;
}
#define STS64(a, x, y) \
    asm volatile("st.shared.v2.b32 [%0], {%1, %2};" :: "r"(a), "r"(x), "r"(y) : "memory")

__device__ __forceinline__ void ldsm4(uint32_t* r, uint32_t addr) {
    asm volatile("ldmatrix.sync.aligned.m8n8.x4.shared.b16 {%0,%1,%2,%3}, [%4];"
        : "=r"(r[0]), "=r"(r[1]), "=r"(r[2]), "=r"(r[3]) : "r"(addr));
}
__device__ __forceinline__ void mma16816(float* d, const uint32_t* a, const uint32_t* b) {
    asm volatile(
        "mma.sync.aligned.m16n8k16.row.col.f32.bf16.bf16.f32 "
        "{%0,%1,%2,%3}, {%4,%5,%6,%7}, {%8,%9}, {%0,%1,%2,%3};"
        : "+f"(d[0]), "+f"(d[1]), "+f"(d[2]), "+f"(d[3])
        : "r"(a[0]), "r"(a[1]), "r"(a[2]), "r"(a[3]), "r"(b[0]), "r"(b[1]));
}
// packed fp32x2 ops (sm_100+)
__device__ __forceinline__ void ffma2(unsigned long long& d,
                                      unsigned long long a, unsigned long long b) {
    asm("fma.rn.f32x2 %0, %1, %2, %0;" : "+l"(d) : "l"(a), "l"(b));
}
__device__ __forceinline__ unsigned long long pack2(float x, float y) {
    unsigned long long r;
    asm("mov.b64 %0, {%1, %2};" : "=l"(r) : "f"(x), "f"(y));
    return r;
}
__device__ __forceinline__ void unpack2(unsigned long long v, float& x, float& y) {
    asm("mov.b64 {%0, %1}, %2;" : "=f"(x), "=f"(y) : "l"(v));
}

// ---------------- bf16-split tensor-core GEMM (R3-proven config) ----------
template <int BN>
__global__ __launch_bounds__(256) void tgemm(
    const float* __restrict__ A, const float* __restrict__ B,
    const float* __restrict__ bias, float* __restrict__ C,
    int K, int lda, int ldb, int ldc,
    long long sA1, long long sA2, long long sB1, long long sB2,
    long long sC1, long long sC2, long long sBias1, long long sBias2,
    int ngroup, float alpha)
{
    constexpr int WGM = (BN == 128) ? 4 : 8;
    constexpr int WGN = (BN == 128) ? 2 : 1;
    constexpr int WTM = 128 / WGM;
    constexpr int WTN = BN / WGN;
    constexpr int MB  = WTM / 16;
    constexpr int NB  = WTN / 8;
    constexpr int NB2 = WTN / 16;
    constexpr int A_MAT = 128 * 80;
    constexpr int B_MAT = BN * 80;
    constexpr int BUFSZ = 2 * A_MAT + 2 * B_MAT;
    constexpr int NB4B = BN / 32;

    extern __shared__ char smem[];
    const uint32_t sb = smem_u32(smem);

    const int t = threadIdx.x;
    const int wid = t >> 5, lane = t & 31;
    const int wm = wid % WGM, wn = wid / WGM;

    const int z = blockIdx.z;
    const int bb = z / ngroup;
    const int gg = z - bb * ngroup;
    A += bb * sA1 + gg * sA2;
    B += bb * sB1 + gg * sB2;
    C += bb * sC1 + gg * sC2;
    if (bias) bias += bb * sBias1 + gg * sBias2;

    const int m0 = blockIdx.y * 128;
    const int n0 = blockIdx.x * BN;

    float4 pa[4];
    float4 pb[NB4B];

    auto ldgA = [&](int c) {
        const int k0 = c * 32;
#pragma unroll
        for (int r = 0; r < 4; r++) {
            int f = r * 256 + t, row = f >> 3, seg = f & 7;
            pa[r] = *(const float4*)(A + (size_t)(m0 + row) * lda + k0 + seg * 4);
        }
    };
    auto ldgB = [&](int c) {
        const int k0 = c * 32;
#pragma unroll
        for (int r = 0; r < NB4B; r++) {
            int f = r * 256 + t, row = f >> 3, seg = f & 7;
            pb[r] = *(const float4*)(B + (size_t)(n0 + row) * ldb + k0 + seg * 4);
        }
    };
    auto sts = [&](int buf) {
        const uint32_t base = sb + buf * BUFSZ;
#pragma unroll
        for (int r = 0; r < 4; r++) {
            int f = r * 256 + t, row = f >> 3, seg = f & 7;
            float4 v = pa[r];
            uint32_t h01 = pack_bf(v.x, v.y);
            uint32_t h23 = pack_bf(v.z, v.w);
            float hx = __uint_as_float(h01 << 16);
            float hy = __uint_as_float(h01 & 0xFFFF0000u);
            float hz = __uint_as_float(h23 << 16);
            float hw = __uint_as_float(h23 & 0xFFFF0000u);
            uint32_t l01 = pack_bf(v.x - hx, v.y - hy);
            uint32_t l23 = pack_bf(v.z - hz, v.w - hw);
            uint32_t off = base + row * 80 + seg * 8;
            STS64(off, h01, h23);
            STS64(off + A_MAT, l01, l23);
        }
#pragma unroll
        for (int r = 0; r < NB4B; r++) {
            int f = r * 256 + t, row = f >> 3, seg = f & 7;
            float4 v = pb[r];
            uint32_t h01 = pack_bf(v.x, v.y);
            uint32_t h23 = pack_bf(v.z, v.w);
            float hx = __uint_as_float(h01 << 16);
            float hy = __uint_as_float(h01 & 0xFFFF0000u);
            float hz = __uint_as_float(h23 << 16);
            float hw = __uint_as_float(h23 & 0xFFFF0000u);
            uint32_t l01 = pack_bf(v.x - hx, v.y - hy);
            uint32_t l23 = pack_bf(v.z - hz, v.w - hw);
            uint32_t off = base + 2 * A_MAT + row * 80 + seg * 8;
            STS64(off, h01, h23);
            STS64(off + B_MAT, l01, l23);
        }
    };

    float acc[MB][NB][4];
#pragma unroll
    for (int i = 0; i < MB; i++)
#pragma unroll
        for (int j = 0; j < NB; j++)
#pragma unroll
            for (int q = 0; q < 4; q++) acc[i][j][q] = 0.f;

    const uint32_t a_lane = (uint32_t)((lane & 15) * 80 + (lane >> 4) * 16);
    const uint32_t b_lane = (uint32_t)(((lane & 7) + ((lane >> 4) << 3)) * 80
                                       + ((lane >> 3) & 1) * 16);

    auto compute = [&](int buf) {
        const uint32_t base = sb + buf * BUFSZ;
#pragma unroll
        for (int ks = 0; ks < 2; ks++) {
            const uint32_t ko = ks * 32;
            uint32_t Ah[MB][4], Al[MB][4], Bh[NB][2], Bl[NB][2];
#pragma unroll
            for (int mb = 0; mb < MB; mb++) {
                uint32_t ad = base + (wm * WTM + mb * 16) * 80 + a_lane + ko;
                ldsm4(Ah[mb], ad);
                ldsm4(Al[mb], ad + A_MAT);
            }
#pragma unroll
            for (int n2 = 0; n2 < NB2; n2++) {
                uint32_t bd = base + 2 * A_MAT + (wn * WTN + n2 * 16) * 80 + b_lane + ko;
                ldsm4(&Bh[2 * n2][0], bd);
                ldsm4(&Bl[2 * n2][0], bd + B_MAT);
            }
#pragma unroll
            for (int mb = 0; mb < MB; mb++)
#pragma unroll
                for (int nb = 0; nb < NB; nb++) {
                    mma16816(acc[mb][nb], Ah[mb], Bh[nb]);
                    mma16816(acc[mb][nb], Ah[mb], Bl[nb]);
                    mma16816(acc[mb][nb], Al[mb], Bh[nb]);
                }
        }
    };

    const int NC = K >> 5;
    ldgA(0); ldgB(0);
    sts(0);
    if (NC > 1) { ldgA(1); ldgB(1); }
    __syncthreads();

    for (int c = 0; c < NC; c++) {
        compute(c & 1);
        __syncthreads();
        if (c + 1 < NC) {
            sts((c + 1) & 1);
            __syncthreads();
            if (c + 2 < NC) { ldgA(c + 2); ldgB(c + 2); }
        }
    }

    const int er = lane >> 2, ec = (lane & 3) * 2;
#pragma unroll
    for (int mb = 0; mb < MB; mb++) {
#pragma unroll
        for (int nb = 0; nb < NB; nb++) {
            const int m = m0 + wm * WTM + mb * 16 + er;
            const int n = n0 + wn * WTN + nb * 8 + ec;
            float b0 = 0.f, b1 = 0.f;
            if (bias) { b0 = bias[n]; b1 = bias[n + 1]; }
            float2 v0, v1;
            v0.x = alpha * acc[mb][nb][0] + b0;
            v0.y = alpha * acc[mb][nb][1] + b1;
            v1.x = alpha * acc[mb][nb][2] + b0;
            v1.y = alpha * acc[mb][nb][3] + b1;
            *(float2*)(C + (size_t)m * ldc + n) = v0;
            *(float2*)(C + (size_t)(m + 8) * ldc + n) = v1;
        }
    }
}

// ---------------- fused poslogit + softmax --------------------------------
// One block per (n, b). 4 parts per thread, packed f32x2 posfeat matvec,
// then in-register softmax over each of the 16 group-rows (block reduction
// through a tiny 1KB smem buffer). L is read once (att) and written once.
__global__ __launch_bounds__(256) void poslogit_kernel(
    const float* __restrict__ rois, const float* __restrict__ part_rois,
    const float* __restrict__ Wg_w, const float* __restrict__ Wg_b,
    float* __restrict__ L)
{
    __shared__ ulonglong2 wgp[256];
    __shared__ unsigned long long wbp[8];
    __shared__ float red[16][8];     // [g][warp] reduction buffer

    const int t = threadIdx.x;
    const int w = t >> 5, lane = t & 31;
    {
        const int g2 = t & 7, j = (t >> 3) & 7, i = t >> 6;
        const int r0 = (2 * g2) * 64, r1 = (2 * g2 + 1) * 64;
        ulonglong2 wv;
        wv.x = pack2(Wg_w[r0 + i * 16 + j],     Wg_w[r1 + i * 16 + j]);
        wv.y = pack2(Wg_w[r0 + i * 16 + 8 + j], Wg_w[r1 + i * 16 + 8 + j]);
        wgp[t] = wv;
        if (t < 8) wbp[t] = pack2(Wg_b[2 * t], Wg_b[2 * t + 1]);
    }

    const int n = blockIdx.x;
    const int b = blockIdx.y;
    const int ng = b * 1024 + n;

    const float xmin = rois[ng * 5 + 1];
    const float ymin = rois[ng * 5 + 2];
    const float xmax = rois[ng * 5 + 3];
    const float ymax = rois[ng * 5 + 4];
    const float bw = xmax - xmin + 1.f;
    const float bh = ymax - ymin + 1.f;
    const float cx = 0.5f * (xmin + xmax);
    const float cy = 0.5f * (ymin + ymax);

    float pos[4][4];
#pragma unroll
    for (int pp = 0; pp < 4; pp++) {
        const int pg = b * 1024 + pp * 256 + t;
        const float pxmin = part_rois[pg * 5 + 1];
        const float pymin = part_rois[pg * 5 + 2];
        const float pxmax = part_rois[pg * 5 + 3];
        const float pymax = part_rois[pg * 5 + 4];
        const float pw = pxmax - pxmin + 1.f;
        const float ph = pymax - pymin + 1.f;
        const float pcx = 0.5f * (pxmin + pxmax);
        const float pcy = 0.5f * (pymin + pymax);
        float dx = fabsf((cx - pcx) / bw);
        float dy = fabsf((cy - pcy) / bh);
        pos[pp][0] = __logf(fmaxf(dx, 1e-3f));
        pos[pp][1] = __logf(fmaxf(dy, 1e-3f));
        pos[pp][2] = __logf(pw / bw);
        pos[pp][3] = __logf(ph / bh);
    }
    __syncthreads();

    const float inv_em[8] = {
        1.0f, 0.42169651f, 0.17782794f, 0.074989424f,
        0.031622777f, 0.013335215f, 0.0056234133f, 0.0023713737f};

    unsigned long long acc2[4][8];
#pragma unroll
    for (int pp = 0; pp < 4; pp++)
#pragma unroll
        for (int g2 = 0; g2 < 8; g2++) acc2[pp][g2] = wbp[g2];

#pragma unroll
    for (int i = 0; i < 4; i++) {
#pragma unroll
        for (int j = 0; j < 8; j++) {
            unsigned long long s2[4], c2[4];
#pragma unroll
            for (int pp = 0; pp < 4; pp++) {
                float s, c;
                __sincosf(100.f * pos[pp][i] * inv_em[j], &s, &c);
                s2[pp] = pack2(s, s);
                c2[pp] = pack2(c, c);
            }
            const ulonglong2* wrow = &wgp[(i * 8 + j) * 8];
#pragma unroll
            for (int g2 = 0; g2 < 8; g2++) {
                ulonglong2 wv = wrow[g2];
#pragma unroll
                for (int pp = 0; pp < 4; pp++) {
                    ffma2(acc2[pp][g2], s2[pp], wv.x);
                    ffma2(acc2[pp][g2], c2[pp], wv.y);
                }
            }
        }
    }

    // logits: acc2 <- att(L) + log(max(posfeat, 1e-6))
    const size_t base = ((size_t)ng * 16) * 1024 + t;
#pragma unroll
    for (int pp = 0; pp < 4; pp++) {
#pragma unroll
        for (int g2 = 0; g2 < 8; g2++) {
            float a0, a1;
            unpack2(acc2[pp][g2], a0, a1);
            a0 = __logf(fmaxf(a0, 1e-6f)) + L[base + (size_t)(2 * g2) * 1024 + pp * 256];
            a1 = __logf(fmaxf(a1, 1e-6f)) + L[base + (size_t)(2 * g2 + 1) * 1024 + pp * 256];
            acc2[pp][g2] = pack2(a0, a1);
        }
    }

    // ---- block max per g ----
#pragma unroll
    for (int g2 = 0; g2 < 8; g2++) {
        float m0 = -1e30f, m1 = -1e30f;
#pragma unroll
        for (int pp = 0; pp < 4; pp++) {
            float a0, a1;
            unpack2(acc2[pp][g2], a0, a1);
            m0 = fmaxf(m0, a0);
            m1 = fmaxf(m1, a1);
        }
#pragma unroll
        for (int o = 16; o > 0; o >>= 1) {
            m0 = fmaxf(m0, __shfl_xor_sync(0xFFFFFFFFu, m0, o));
            m1 = fmaxf(m1, __shfl_xor_sync(0xFFFFFFFFu, m1, o));
        }
        if (lane == 0) { red[2 * g2][w] = m0; red[2 * g2 + 1][w] = m1; }
    }
    __syncthreads();
    float mx[16];
#pragma unroll
    for (int g = 0; g < 16; g++) {
        float4 r0 = *(const float4*)&red[g][0];
        float4 r1 = *(const float4*)&red[g][4];
        mx[g] = fmaxf(fmaxf(fmaxf(r0.x, r0.y), fmaxf(r0.z, r0.w)),
                      fmaxf(fmaxf(r1.x, r1.y), fmaxf(r1.z, r1.w)));
    }
    __syncthreads();

    // ---- exp + block sum per g ----
#pragma unroll
    for (int g2 = 0; g2 < 8; g2++) {
        float s0 = 0.f, s1 = 0.f;
#pragma unroll
        for (int pp = 0; pp < 4; pp++) {
            float a0, a1;
            unpack2(acc2[pp][g2], a0, a1);
            a0 = __expf(a0 - mx[2 * g2]);
            a1 = __expf(a1 - mx[2 * g2 + 1]);
            acc2[pp][g2] = pack2(a0, a1);
            s0 += a0;
            s1 += a1;
        }
#pragma unroll
        for (int o = 16; o > 0; o >>= 1) {
            s0 += __shfl_xor_sync(0xFFFFFFFFu, s0, o);
            s1 += __shfl_xor_sync(0xFFFFFFFFu, s1, o);
        }
        if (lane == 0) { red[2 * g2][w] = s0; red[2 * g2 + 1][w] = s1; }
    }
    __syncthreads();
#pragma unroll
    for (int g = 0; g < 16; g++) {
        float4 r0 = *(const float4*)&red[g][0];
        float4 r1 = *(const float4*)&red[g][4];
        mx[g] = 1.f / (r0.x + r0.y + r0.z + r0.w + r1.x + r1.y + r1.z + r1.w);
    }

    // ---- scale + store ----
#pragma unroll
    for (int pp = 0; pp < 4; pp++) {
#pragma unroll
        for (int g2 = 0; g2 < 8; g2++) {
            float a0, a1;
            unpack2(acc2[pp][g2], a0, a1);
            L[base + (size_t)(2 * g2) * 1024 + pp * 256]     = a0 * mx[2 * g2];
            L[base + (size_t)(2 * g2 + 1) * 1024 + pp * 256] = a1 * mx[2 * g2 + 1];
        }
    }
}

// ---------------- host ----------------------------------------------------
extern "C" void kernel_launch(void* const* d_in, const int* in_sizes, int n_in,
                              void* d_out, int out_size)
{
    const float* rois       = (const float*)d_in[0];
    const float* part_rois  = (const float*)d_in[1];
    const float* box_feats  = (const float*)d_in[2];
    const float* part_feats = (const float*)d_in[3];
    const float* Wg_w       = (const float*)d_in[4];
    const float* Wg_b       = (const float*)d_in[5];
    const float* Wq_w       = (const float*)d_in[6];
    const float* Wq_b       = (const float*)d_in[7];
    const float* Wk_w       = (const float*)d_in[8];
    const float* Wk_b       = (const float*)d_in[9];
    const float* conv_w     = (const float*)d_in[10];
    const float* conv_b     = (const float*)d_in[11];
    float* out = (float*)d_out;

    float *q, *k, *pw, *L;
    cudaGetSymbolAddress((void**)&q,  g_q);
    cudaGetSymbolAddress((void**)&k,  g_k);
    cudaGetSymbolAddress((void**)&pw, g_pw);
    cudaGetSymbolAddress((void**)&L,  g_L);

    const int SM128 = 2 * (2 * 128 * 80 + 2 * 128 * 80); // 81920
    const int SM64  = 2 * (2 * 128 * 80 + 2 * 64 * 80);  // 61440
    cudaFuncSetAttribute(tgemm<128>, cudaFuncAttributeMaxDynamicSharedMemorySize, SM128);
    cudaFuncSetAttribute(tgemm<64>,  cudaFuncAttributeMaxDynamicSharedMemorySize, SM64);

    // merged q & k projections via pointer-difference batch strides
    {
        long long dA = (long long)(part_feats - box_feats);
        long long dB = (long long)(Wk_w - Wq_w);
        long long dBias = (long long)(Wk_b - Wq_b);
        long long dC = (long long)(k - q);
        tgemm<128><<<dim3(8, 16, 2), 256, SM128>>>(
            box_feats, Wq_w, Wq_b, q, 1024, 1024, 1024, 1024,
            dA, 0, dB, 0, dC, 0, dBias, 0, 1, 1.f);
    }

    // pwT = conv_w @ part_feats^T         M=1024 N=2048 K=1024  -> [GE, P]
    tgemm<128><<<dim3(16, 8, 1), 256, SM128>>>(
        conv_w, part_feats, nullptr, pw, 1024, 1024, 1024, 2048,
        0, 0, 0, 0, 0, 0, 0, 0, 1, 1.f);

    // att/16 into L: 32 batches (b,g): M=1024 N=1024 K=64
    tgemm<128><<<dim3(8, 8, 32), 256, SM128>>>(
        q, k, nullptr, L, 64, 1024, 1024, 16384,
        1048576LL, 64LL, 1048576LL, 64LL,
        16777216LL, 1024LL, 0LL, 0LL, 16, 1.f / 16.f);

    // L = softmax(att + log(posfeat))  — fused, one block per (n,b)
    poslogit_kernel<<<dim3(1024, 2), 256>>>(rois, part_rois, Wg_w, Wg_b, L);

    // rel = sm @ pwT^T + conv_b: 32 batches: M=1024 N=64 K=1024
    tgemm<64><<<dim3(1, 8, 32), 256, SM64>>>(
        L, pw, conv_b, out, 1024, 16384, 2048, 1024,
        16777216LL, 1024LL, 1024LL, 131072LL,
        1048576LL, 64LL, 0LL, 64LL, 16, 1.f);
}